// round 14
// baseline (speedup 1.0000x reference)
#include <cuda_runtime.h>
#include <cstdint>

// Spatial GCN (24x24 grid, adj = D^-1 A + I => 5-point stencil) + weight
// + BatchNorm2d(train) + LeakyReLU(0.2), fully fused, single plain launch.
//
// R14: one 576-thread CTA per channel, ZERO data staging, no clusters, no
// cross-CTA rendezvous, tiny static smem (replay-tax free). Pass 1 streams
// x straight from gmem (ctr/up/dn LDG.128, left/right via warp shuffle with
// boundary fallbacks -- edge coefficients are exactly 0, so cross-plane
// shuffle garbage is annihilated) and accumulates BN statistics without
// storing y. After one block reduction, pass 2 recomputes the stencil from
// the now L2-resident x (__ldcs evict-first) and writes the normalized
// result with __stcs (streaming, minimal L2 pollution).

#define GRID_N  24
#define NN      576
#define NQ      144              // float4 quads per plane
#define BATCH   64
#define NSLOT   4                // plane slots (576 = 4 * 144)
#define KPT     (BATCH / NSLOT)  // 16 planes per thread
#define NTHR    576
#define BN_EPS  1e-4f
#define SLOPE   0.2f

__device__ __forceinline__ float invdeg(int i, int j) {
    const int d = 2 + (int)(i > 0 && i < GRID_N - 1) + (int)(j > 0 && j < GRID_N - 1);
    return (d == 2) ? 0.5f : ((d == 3) ? (1.f / 3.f) : 0.25f);
}

__global__ __launch_bounds__(NTHR, 2)
void gcn_bn_lrelu_kernel(const float* __restrict__ x,
                         const float* __restrict__ weight,
                         const float* __restrict__ gamma,
                         const float* __restrict__ beta,
                         float* __restrict__ out,
                         int C)
{
    __shared__ float red[40];
    __shared__ float s_sb[2];

    const int c    = blockIdx.x;
    const int t    = threadIdx.x;              // 0..575
    const int lane = t & 31;
    const int ph   = t / NQ;                   // plane slot 0..3
    const int q    = t - ph * NQ;              // quad 0..143
    const int row  = q / 6;
    const int col4 = q - row * 6;
    const int l0   = 4 * q;

    // ---- analytic stencil coefficients folded with weight ----
    const float4 w4 = ((const float4*)(weight + (size_t)c * NN))[q];
    float cL[4], cR[4], cU[4], cD[4];
#pragma unroll
    for (int e = 0; e < 4; ++e) {
        const int j = 4 * col4 + e;
        const float we = (e == 0) ? w4.x : (e == 1) ? w4.y : (e == 2) ? w4.z : w4.w;
        cL[e] = (j > 0)           ? invdeg(row, j - 1) * we : 0.f;
        cR[e] = (j < GRID_N - 1)  ? invdeg(row, j + 1) * we : 0.f;
        cU[e] = (row > 0)         ? invdeg(row - 1, j) * we : 0.f;
        cD[e] = (row < GRID_N -1) ? invdeg(row + 1, j) * we : 0.f;
    }
    const int dU = (row > 0) ? -6 : 0;                 // quad offset up
    const int dD = (row < GRID_N - 1) ? 6 : 0;         // quad offset down
    const bool fbL = (lane == 0)  && (col4 > 0);       // shuffle fallbacks
    const bool fbR = (lane == 31) && (col4 < 5);

    const float4* __restrict__ x4 = (const float4*)x;
    float4* __restrict__ out4 = (float4*)out;

    // 32-bit indexing: max index 64*512*144 < 2^31
    const unsigned idx0 = (unsigned)(ph * C + c) * NQ + q;   // plane b = ph
    const unsigned step = 4u * (unsigned)C * NQ;             // b += 4

#define STENCIL_Y(ctr, up, dn, lft, rgt, Y)                                   \
    {                                                                         \
        Y.x = w4.x*ctr.x; Y.x = fmaf(cL[0], lft,   Y.x); Y.x = fmaf(cR[0], ctr.y, Y.x); \
        Y.x = fmaf(cU[0], up.x, Y.x); Y.x = fmaf(cD[0], dn.x, Y.x);           \
        Y.y = w4.y*ctr.y; Y.y = fmaf(cL[1], ctr.x, Y.y); Y.y = fmaf(cR[1], ctr.z, Y.y); \
        Y.y = fmaf(cU[1], up.y, Y.y); Y.y = fmaf(cD[1], dn.y, Y.y);           \
        Y.z = w4.z*ctr.z; Y.z = fmaf(cL[2], ctr.y, Y.z); Y.z = fmaf(cR[2], ctr.w, Y.z); \
        Y.z = fmaf(cU[2], up.z, Y.z); Y.z = fmaf(cD[2], dn.z, Y.z);           \
        Y.w = w4.w*ctr.w; Y.w = fmaf(cL[3], ctr.z, Y.w); Y.w = fmaf(cR[3], rgt, Y.w);   \
        Y.w = fmaf(cU[3], up.w, Y.w); Y.w = fmaf(cD[3], dn.w, Y.w);           \
    }

    // ---- pass 1: stream x, accumulate stats (y not stored) ----
    float sum = 0.f, sq = 0.f;
    {
        unsigned idx = idx0;
#pragma unroll 4
        for (int k = 0; k < KPT; ++k) {
            const float4 ctr = x4[idx];
            const float4 up  = x4[idx + dU];
            const float4 dn  = x4[idx + dD];
            float lft = __shfl_up_sync(0xffffffffu,  ctr.w, 1);
            float rgt = __shfl_down_sync(0xffffffffu, ctr.x, 1);
            if (fbL) lft = ((const float*)(x4 + (idx - q)))[l0 - 1];
            if (fbR) rgt = ((const float*)(x4 + (idx - q)))[l0 + 4];

            float4 y;
            STENCIL_Y(ctr, up, dn, lft, rgt, y);
            sum += (y.x + y.y) + (y.z + y.w);
            sq = fmaf(y.x, y.x, sq); sq = fmaf(y.y, y.y, sq);
            sq = fmaf(y.z, y.z, sq); sq = fmaf(y.w, y.w, sq);
            idx += step;
        }
    }

    // ---- block reduction -> scale / bias ----
#pragma unroll
    for (int off = 16; off > 0; off >>= 1) {
        sum += __shfl_down_sync(0xffffffffu, sum, off);
        sq  += __shfl_down_sync(0xffffffffu, sq,  off);
    }
    const int warp = t >> 5;                   // 18 warps
    if (lane == 0) { red[warp] = sum; red[20 + warp] = sq; }
    __syncthreads();
    if (t == 0) {
        float s = 0.f, qq = 0.f;
#pragma unroll
        for (int wi = 0; wi < NTHR / 32; ++wi) { s += red[wi]; qq += red[20 + wi]; }
        const float inv_n = 1.f / (float)(BATCH * NN);
        float mean = s * inv_n;
        float var  = fmaf(qq, inv_n, -mean * mean);
        float rstd = rsqrtf(var + BN_EPS);
        float sc   = gamma[c] * rstd;
        s_sb[0] = sc;
        s_sb[1] = fmaf(-mean, sc, beta[c]);
    }
    __syncthreads();
    const float sc = s_sb[0], bi = s_sb[1];

    // ---- pass 2: recompute stencil from L2-resident x, normalize, store ----
    {
        unsigned idx = idx0;
#pragma unroll 4
        for (int k = 0; k < KPT; ++k) {
            const float4 ctr = __ldcs(x4 + idx);
            const float4 up  = __ldcs(x4 + idx + dU);
            const float4 dn  = __ldcs(x4 + idx + dD);
            float lft = __shfl_up_sync(0xffffffffu,  ctr.w, 1);
            float rgt = __shfl_down_sync(0xffffffffu, ctr.x, 1);
            if (fbL) lft = ((const float*)(x4 + (idx - q)))[l0 - 1];
            if (fbR) rgt = ((const float*)(x4 + (idx - q)))[l0 + 4];

            float4 y;
            STENCIL_Y(ctr, up, dn, lft, rgt, y);
            float4 v;
            v.x = fmaf(y.x, sc, bi); v.y = fmaf(y.y, sc, bi);
            v.z = fmaf(y.z, sc, bi); v.w = fmaf(y.w, sc, bi);
            v.x = (v.x >= 0.f) ? v.x : SLOPE * v.x;
            v.y = (v.y >= 0.f) ? v.y : SLOPE * v.y;
            v.z = (v.z >= 0.f) ? v.z : SLOPE * v.z;
            v.w = (v.w >= 0.f) ? v.w : SLOPE * v.w;
            __stcs(out4 + idx, v);
            idx += step;
        }
    }
}

extern "C" void kernel_launch(void* const* d_in, const int* in_sizes, int n_in,
                              void* d_out, int out_size)
{
    const float* x      = (const float*)d_in[0];
    const float* weight = (const float*)d_in[2];
    const float* gamma  = (const float*)d_in[3];
    const float* beta   = (const float*)d_in[4];
    float* out = (float*)d_out;

    const int C = in_sizes[2] / NN;            // 512
    gcn_bn_lrelu_kernel<<<C, NTHR>>>(x, weight, gamma, beta, out, C);
}

// round 15
// speedup vs baseline: 1.0119x; 1.0119x over previous
#include <cuda_runtime.h>
#include <cuda_pipeline_primitives.h>
#include <cstdint>

// Spatial GCN (24x24 grid, adj = D^-1 A + I => 5-point stencil) + weight
// + BatchNorm2d(train) + LeakyReLU(0.2), fully fused, single plain launch.
//
// R15: the measured-best recipe recombined.
//  - 576-thread CTAs, 4 per channel, 16 planes staged in 36.9KB STATIC smem
//    (static => no cudaFuncSetAttribute carveout reconfig => ~0.7us launch
//    overhead instead of ~5.4us measured for all >48KB dynamic variants).
//  - x loaded via 2 cp.async groups of 8 planes; each thread stencils 4
//    planes (2 per barrier window, ILP 2); only ~4 barriers total.
//  - y kept in 4 float4 REGISTERS: no smem writeback, no apply-pass LDS.
//  - per-channel BN stats via the proven gmem rendezvous (publish ->
//    atomic arrive -> acquire spin -> fixed-order combine -> last reader
//    resets counters for graph replay).

#define GRID_N  24
#define NN      576
#define NQ      144              // float4 quads per plane
#define BATCH   64
#define CSPLIT  4                // CTAs per channel
#define PLANES  (BATCH / CSPLIT) // 16 planes per CTA
#define NTHR    576
#define BN_EPS  1e-4f
#define SLOPE   0.2f
#define MAXC    512

// rendezvous scratch (zero at load; self-reset to zero every launch)
__device__ float    g_part[MAXC * CSPLIT * 2];
__device__ unsigned g_cnt[MAXC];
__device__ unsigned g_done[MAXC];

__device__ __forceinline__ float invdeg(int i, int j) {
    const int d = 2 + (int)(i > 0 && i < GRID_N - 1) + (int)(j > 0 && j < GRID_N - 1);
    return (d == 2) ? 0.5f : ((d == 3) ? (1.f / 3.f) : 0.25f);
}

__global__ __launch_bounds__(NTHR, 2)
void gcn_bn_lrelu_kernel(const float* __restrict__ x,
                         const float* __restrict__ weight,
                         const float* __restrict__ gamma,
                         const float* __restrict__ beta,
                         float* __restrict__ out,
                         int C)
{
    __shared__ float buf[PLANES * NN];         // 36864 B, static
    __shared__ float red[64];
    __shared__ float s_sb[2];

    const int c    = blockIdx.x / CSPLIT;
    const int rank = blockIdx.x - c * CSPLIT;  // 0..3
    const int t    = threadIdx.x;              // 0..575
    const int lane = t & 31;
    const int pq   = t / NQ;                   // 0..3
    const int q    = t - pq * NQ;              // quad 0..143
    const int row  = q / 6;
    const int col4 = q - row * 6;
    const int l0   = 4 * q;

    // 32-bit global index helpers (max index < 2^31)
    const unsigned planeStride = (unsigned)C * NQ;          // float4 units
    const unsigned base0 = (unsigned)(rank * PLANES) * planeStride
                         + (unsigned)c * NQ + q;            // plane lp=0

    // ---- prologue: 2 cp.async groups of 8 planes (4 per thread each) ----
    const float4* __restrict__ x4 = (const float4*)x;
    float4* buf4 = (float4*)buf;
#pragma unroll
    for (int g = 0; g < 2; ++g) {
#pragma unroll
        for (int h = 0; h < 2; ++h) {
            const int lp = g * 8 + pq + h * 4;              // local plane
            __pipeline_memcpy_async(&buf4[(unsigned)lp * NQ + q],
                                    x4 + (base0 + (unsigned)lp * planeStride), 16);
        }
        __pipeline_commit();
    }

    // ---- analytic coefficients folded with weight ----
    const float4 w4 = ((const float4*)(weight + (size_t)c * NN))[q];
    float cL[4], cR[4], cU[4], cD[4];
#pragma unroll
    for (int e = 0; e < 4; ++e) {
        const int j = 4 * col4 + e;
        const float we = (e == 0) ? w4.x : (e == 1) ? w4.y : (e == 2) ? w4.z : w4.w;
        cL[e] = (j > 0)           ? invdeg(row, j - 1) * we : 0.f;
        cR[e] = (j < GRID_N - 1)  ? invdeg(row, j + 1) * we : 0.f;
        cU[e] = (row > 0)         ? invdeg(row - 1, j) * we : 0.f;
        cD[e] = (row < GRID_N -1) ? invdeg(row + 1, j) * we : 0.f;
    }
    const int oL = (col4 > 0) ? l0 - 1 : l0;
    const int oR = (col4 < 5) ? l0 + 4 : l0;
    const int qU = (row > 0) ? q - 6 : q;
    const int qD = (row < GRID_N - 1) ? q + 6 : q;

#define DO_STENCIL(LP, Y)                                                     \
    {                                                                         \
        const float*  xb  = buf + (unsigned)(LP) * NN;                        \
        const float4* xb4 = (const float4*)xb;                                \
        const float4 ctr = xb4[q];                                            \
        const float4 up  = xb4[qU];                                           \
        const float4 dn  = xb4[qD];                                           \
        const float  lft = xb[oL];                                            \
        const float  rgt = xb[oR];                                            \
        Y.x = w4.x*ctr.x; Y.x = fmaf(cL[0], lft,   Y.x); Y.x = fmaf(cR[0], ctr.y, Y.x); \
        Y.x = fmaf(cU[0], up.x, Y.x); Y.x = fmaf(cD[0], dn.x, Y.x);           \
        Y.y = w4.y*ctr.y; Y.y = fmaf(cL[1], ctr.x, Y.y); Y.y = fmaf(cR[1], ctr.z, Y.y); \
        Y.y = fmaf(cU[1], up.y, Y.y); Y.y = fmaf(cD[1], dn.y, Y.y);           \
        Y.z = w4.z*ctr.z; Y.z = fmaf(cL[2], ctr.y, Y.z); Y.z = fmaf(cR[2], ctr.w, Y.z); \
        Y.z = fmaf(cU[2], up.z, Y.z); Y.z = fmaf(cD[2], dn.z, Y.z);           \
        Y.w = w4.w*ctr.w; Y.w = fmaf(cL[3], ctr.z, Y.w); Y.w = fmaf(cR[3], rgt, Y.w);   \
        Y.w = fmaf(cU[3], up.w, Y.w); Y.w = fmaf(cD[3], dn.w, Y.w);           \
    }

#define ACC(Y)                                                                \
    {                                                                         \
        sum += (Y.x + Y.y) + (Y.z + Y.w);                                     \
        sq = fmaf(Y.x, Y.x, sq); sq = fmaf(Y.y, Y.y, sq);                     \
        sq = fmaf(Y.z, Y.z, sq); sq = fmaf(Y.w, Y.w, sq);                     \
    }

    // ---- stats pass: 2 windows, 2 plane-stencils each; y stays in regs ----
    float sum = 0.f, sq = 0.f;
    float4 y0, y1, y2, y3;

    __pipeline_wait_prior(1);                  // group 0 resident
    __syncthreads();
    DO_STENCIL(pq,     y0); ACC(y0);
    DO_STENCIL(pq + 4, y1); ACC(y1);

    __pipeline_wait_prior(0);                  // group 1 resident
    __syncthreads();
    DO_STENCIL(8 + pq,     y2); ACC(y2);
    DO_STENCIL(8 + pq + 4, y3); ACC(y3);

    // ---- block reduction of this CTA's partial (sum, sq) ----
#pragma unroll
    for (int off = 16; off > 0; off >>= 1) {
        sum += __shfl_down_sync(0xffffffffu, sum, off);
        sq  += __shfl_down_sync(0xffffffffu, sq,  off);
    }
    const int warp = t >> 5;                   // 18 warps
    if (lane == 0) { red[warp] = sum; red[32 + warp] = sq; }
    __syncthreads();

    // ---- gmem rendezvous across the channel's 4 CTAs ----
    if (t == 0) {
        float s = 0.f, qq = 0.f;
#pragma unroll
        for (int wi = 0; wi < NTHR / 32; ++wi) { s += red[wi]; qq += red[32 + wi]; }
        float* slot = g_part + ((size_t)c * CSPLIT + rank) * 2;
        slot[0] = s; slot[1] = qq;
        __threadfence();
        atomicAdd(&g_cnt[c], 1u);

        unsigned v;
        do {
            asm volatile("ld.acquire.gpu.u32 %0, [%1];"
                         : "=r"(v) : "l"(&g_cnt[c]) : "memory");
        } while (v < CSPLIT);

        float st = 0.f, qt = 0.f;
        const float* base = g_part + (size_t)c * CSPLIT * 2;
#pragma unroll
        for (int r = 0; r < CSPLIT; ++r) { st += base[2 * r]; qt += base[2 * r + 1]; }

        const float inv_n = 1.f / (float)(BATCH * NN);
        float mean = st * inv_n;
        float var  = fmaf(qt, inv_n, -mean * mean);
        float rstd = rsqrtf(var + BN_EPS);
        float scv  = gamma[c] * rstd;
        s_sb[0] = scv;
        s_sb[1] = fmaf(-mean, scv, beta[c]);

        __threadfence();
        unsigned d = atomicAdd(&g_done[c], 1u);
        if (d == CSPLIT - 1) {   // last reader resets for the next replay
            asm volatile("st.relaxed.gpu.u32 [%0], %1;" :: "l"(&g_done[c]), "r"(0u) : "memory");
            asm volatile("st.relaxed.gpu.u32 [%0], %1;" :: "l"(&g_cnt[c]),  "r"(0u) : "memory");
        }
    }
    __syncthreads();
    const float sc = s_sb[0], bi = s_sb[1];

    // ---- apply pass: normalize + LeakyReLU straight from registers ----
    float4* __restrict__ out4 = (float4*)out;
#define APPLY_STORE(Y, LP)                                                    \
    {                                                                         \
        float4 v;                                                             \
        v.x = fmaf(Y.x, sc, bi); v.y = fmaf(Y.y, sc, bi);                     \
        v.z = fmaf(Y.z, sc, bi); v.w = fmaf(Y.w, sc, bi);                     \
        v.x = (v.x >= 0.f) ? v.x : SLOPE * v.x;                               \
        v.y = (v.y >= 0.f) ? v.y : SLOPE * v.y;                               \
        v.z = (v.z >= 0.f) ? v.z : SLOPE * v.z;                               \
        v.w = (v.w >= 0.f) ? v.w : SLOPE * v.w;                               \
        out4[base0 + (unsigned)(LP) * planeStride] = v;                       \
    }
    APPLY_STORE(y0, pq);
    APPLY_STORE(y1, pq + 4);
    APPLY_STORE(y2, 8 + pq);
    APPLY_STORE(y3, 8 + pq + 4);
#undef APPLY_STORE
}

extern "C" void kernel_launch(void* const* d_in, const int* in_sizes, int n_in,
                              void* d_out, int out_size)
{
    const float* x      = (const float*)d_in[0];
    const float* weight = (const float*)d_in[2];
    const float* gamma  = (const float*)d_in[3];
    const float* beta   = (const float*)d_in[4];
    float* out = (float*)d_out;

    const int C = in_sizes[2] / NN;            // 512
    gcn_bn_lrelu_kernel<<<C * CSPLIT, NTHR>>>(x, weight, gamma, beta, out, C);
}

// round 16
// speedup vs baseline: 1.1392x; 1.1258x over previous
#include <cuda_runtime.h>
#include <cuda_pipeline_primitives.h>
#include <cstdint>

// Spatial GCN (24x24 grid, adj = D^-1 A + I => 5-point stencil) + weight
// + BatchNorm2d(train) + LeakyReLU(0.2), fully fused, single plain launch.
//
// R16: instruction-count-minimizing point of the proven family.
//  - 1024 CTAs (2 per channel) x 288 threads: 295K threads total (half of
//    R9), 16 planes per thread -> per-thread setup amortizes 2x better.
//  - __launch_bounds__(288, 2) -> 113-reg budget: ALL 16 y quads live in
//    registers (no smem writeback, no apply LDS, no spills at 2 CTAs/SM).
//  - 32 planes staged in 73.7KB dynamic smem via 8 pipelined cp.async
//    groups; buffer is read-only -> 1 barrier per chunk.
//  - per-channel BN stats: proven 2-way gmem rendezvous (publish -> atomic
//    arrive -> acquire spin -> fixed-order combine -> last reader resets).

#define GRID_N  24
#define NN      576
#define NQ      144              // float4 quads per plane
#define BATCH   64
#define CSPLIT  2                // CTAs per channel
#define PLANES  (BATCH / CSPLIT) // 32 planes per CTA
#define PPC     4                // planes per chunk
#define NCHUNK  (PLANES / PPC)   // 8
#define NTHR    288              // 2 plane-slots x 144 quads
#define BN_EPS  1e-4f
#define SLOPE   0.2f
#define MAXC    512

// rendezvous scratch (zero at load; self-reset to zero every launch)
__device__ float    g_part[MAXC * CSPLIT * 2];
__device__ unsigned g_cnt[MAXC];
__device__ unsigned g_done[MAXC];

__device__ __forceinline__ float invdeg(int i, int j) {
    const int d = 2 + (int)(i > 0 && i < GRID_N - 1) + (int)(j > 0 && j < GRID_N - 1);
    return (d == 2) ? 0.5f : ((d == 3) ? (1.f / 3.f) : 0.25f);
}

__global__ __launch_bounds__(NTHR, 2)
void gcn_bn_lrelu_kernel(const float* __restrict__ x,
                         const float* __restrict__ weight,
                         const float* __restrict__ gamma,
                         const float* __restrict__ beta,
                         float* __restrict__ out,
                         int C)
{
    extern __shared__ float buf[];             // PLANES * NN floats (73728 B)
    __shared__ float red[24];
    __shared__ float s_sb[2];

    const int c    = blockIdx.x >> 1;
    const int rank = blockIdx.x & 1;           // 0..1
    const int t    = threadIdx.x;              // 0..287
    const int lane = t & 31;
    const int ph   = t / NQ;                   // plane-slot 0..1
    const int q    = t - ph * NQ;              // quad 0..143
    const int row  = q / 6;
    const int col4 = q - row * 6;
    const int l0   = 4 * q;

    // 32-bit global indexing (max index < 2^31)
    const unsigned planeStride = (unsigned)C * NQ;           // float4 units
    const unsigned base0 = (unsigned)(rank * PLANES) * planeStride
                         + (unsigned)c * NQ + q;             // local plane 0

    // ---- prologue: 8 cp.async groups of 4 planes (2 per thread each) ----
    const float4* __restrict__ x4 = (const float4*)x;
    float4* buf4 = (float4*)buf;
#pragma unroll
    for (int s = 0; s < NCHUNK; ++s) {
#pragma unroll
        for (int h = 0; h < 2; ++h) {
            const int lp = s * PPC + ph + h * 2;             // local plane
            __pipeline_memcpy_async(&buf4[(unsigned)lp * NQ + q],
                                    x4 + (base0 + (unsigned)lp * planeStride), 16);
        }
        __pipeline_commit();
    }

    // ---- analytic coefficients folded with weight ----
    const float4 w4 = ((const float4*)(weight + (size_t)c * NN))[q];
    float cL[4], cR[4], cU[4], cD[4];
#pragma unroll
    for (int e = 0; e < 4; ++e) {
        const int j = 4 * col4 + e;
        const float we = (e == 0) ? w4.x : (e == 1) ? w4.y : (e == 2) ? w4.z : w4.w;
        cL[e] = (j > 0)           ? invdeg(row, j - 1) * we : 0.f;
        cR[e] = (j < GRID_N - 1)  ? invdeg(row, j + 1) * we : 0.f;
        cU[e] = (row > 0)         ? invdeg(row - 1, j) * we : 0.f;
        cD[e] = (row < GRID_N -1) ? invdeg(row + 1, j) * we : 0.f;
    }
    const int oL = (col4 > 0) ? l0 - 1 : l0;
    const int oR = (col4 < 5) ? l0 + 4 : l0;
    const int qU = (row > 0) ? q - 6 : q;
    const int qD = (row < GRID_N - 1) ? q + 6 : q;

#define DO_STENCIL(LP, Y)                                                     \
    {                                                                         \
        const float*  xb  = buf + (unsigned)(LP) * NN;                        \
        const float4* xb4 = (const float4*)xb;                                \
        const float4 ctr = xb4[q];                                            \
        const float4 up  = xb4[qU];                                           \
        const float4 dn  = xb4[qD];                                           \
        const float  lft = xb[oL];                                            \
        const float  rgt = xb[oR];                                            \
        Y.x = w4.x*ctr.x; Y.x = fmaf(cL[0], lft,   Y.x); Y.x = fmaf(cR[0], ctr.y, Y.x); \
        Y.x = fmaf(cU[0], up.x, Y.x); Y.x = fmaf(cD[0], dn.x, Y.x);           \
        Y.y = w4.y*ctr.y; Y.y = fmaf(cL[1], ctr.x, Y.y); Y.y = fmaf(cR[1], ctr.z, Y.y); \
        Y.y = fmaf(cU[1], up.y, Y.y); Y.y = fmaf(cD[1], dn.y, Y.y);           \
        Y.z = w4.z*ctr.z; Y.z = fmaf(cL[2], ctr.y, Y.z); Y.z = fmaf(cR[2], ctr.w, Y.z); \
        Y.z = fmaf(cU[2], up.z, Y.z); Y.z = fmaf(cD[2], dn.z, Y.z);           \
        Y.w = w4.w*ctr.w; Y.w = fmaf(cL[3], ctr.z, Y.w); Y.w = fmaf(cR[3], rgt, Y.w);   \
        Y.w = fmaf(cU[3], up.w, Y.w); Y.w = fmaf(cD[3], dn.w, Y.w);           \
    }

#define ACC(Y)                                                                \
    {                                                                         \
        sum += (Y.x + Y.y) + (Y.z + Y.w);                                     \
        sq = fmaf(Y.x, Y.x, sq); sq = fmaf(Y.y, Y.y, sq);                     \
        sq = fmaf(Y.z, Y.z, sq); sq = fmaf(Y.w, Y.w, sq);                     \
    }

    // ---- stats pass: 8 chunks, 2 plane-stencils each; ALL y in registers ----
    float sum = 0.f, sq = 0.f;
    float4 yv[2 * NCHUNK];                     // 16 float4 = 64 registers
#pragma unroll
    for (int ch = 0; ch < NCHUNK; ++ch) {
        __pipeline_wait_prior(NCHUNK - 1 - ch);
        __syncthreads();                       // chunk ch resident (read-only)
        DO_STENCIL(ch * PPC + ph,     yv[2 * ch]);     ACC(yv[2 * ch]);
        DO_STENCIL(ch * PPC + ph + 2, yv[2 * ch + 1]); ACC(yv[2 * ch + 1]);
    }

    // ---- block reduction of this CTA's partial (sum, sq) ----
#pragma unroll
    for (int off = 16; off > 0; off >>= 1) {
        sum += __shfl_down_sync(0xffffffffu, sum, off);
        sq  += __shfl_down_sync(0xffffffffu, sq,  off);
    }
    const int warp = t >> 5;                   // 9 warps
    if (lane == 0) { red[warp] = sum; red[12 + warp] = sq; }
    __syncthreads();

    // ---- gmem rendezvous across the channel's 2 CTAs ----
    if (t == 0) {
        float s = 0.f, qq = 0.f;
#pragma unroll
        for (int wi = 0; wi < NTHR / 32; ++wi) { s += red[wi]; qq += red[12 + wi]; }
        float* slot = g_part + ((size_t)c * CSPLIT + rank) * 2;
        slot[0] = s; slot[1] = qq;
        __threadfence();
        atomicAdd(&g_cnt[c], 1u);

        unsigned v;
        do {
            asm volatile("ld.acquire.gpu.u32 %0, [%1];"
                         : "=r"(v) : "l"(&g_cnt[c]) : "memory");
        } while (v < CSPLIT);

        float st = 0.f, qt = 0.f;
        const float* base = g_part + (size_t)c * CSPLIT * 2;
#pragma unroll
        for (int r = 0; r < CSPLIT; ++r) { st += base[2 * r]; qt += base[2 * r + 1]; }

        const float inv_n = 1.f / (float)(BATCH * NN);
        float mean = st * inv_n;
        float var  = fmaf(qt, inv_n, -mean * mean);
        float rstd = rsqrtf(var + BN_EPS);
        float scv  = gamma[c] * rstd;
        s_sb[0] = scv;
        s_sb[1] = fmaf(-mean, scv, beta[c]);

        __threadfence();
        unsigned d = atomicAdd(&g_done[c], 1u);
        if (d == CSPLIT - 1) {   // last reader resets for the next replay
            asm volatile("st.relaxed.gpu.u32 [%0], %1;" :: "l"(&g_done[c]), "r"(0u) : "memory");
            asm volatile("st.relaxed.gpu.u32 [%0], %1;" :: "l"(&g_cnt[c]),  "r"(0u) : "memory");
        }
    }
    __syncthreads();
    const float sc = s_sb[0], bi = s_sb[1];

    // ---- apply pass: normalize + LeakyReLU straight from registers ----
    float4* __restrict__ out4 = (float4*)out;
#pragma unroll
    for (int ch = 0; ch < NCHUNK; ++ch) {
#pragma unroll
        for (int h = 0; h < 2; ++h) {
            const int lp = ch * PPC + ph + h * 2;
            float4 y = yv[2 * ch + h];
            float4 v;
            v.x = fmaf(y.x, sc, bi); v.y = fmaf(y.y, sc, bi);
            v.z = fmaf(y.z, sc, bi); v.w = fmaf(y.w, sc, bi);
            v.x = (v.x >= 0.f) ? v.x : SLOPE * v.x;
            v.y = (v.y >= 0.f) ? v.y : SLOPE * v.y;
            v.z = (v.z >= 0.f) ? v.z : SLOPE * v.z;
            v.w = (v.w >= 0.f) ? v.w : SLOPE * v.w;
            out4[base0 + (unsigned)lp * planeStride] = v;
        }
    }
}

extern "C" void kernel_launch(void* const* d_in, const int* in_sizes, int n_in,
                              void* d_out, int out_size)
{
    const float* x      = (const float*)d_in[0];
    const float* weight = (const float*)d_in[2];
    const float* gamma  = (const float*)d_in[3];
    const float* beta   = (const float*)d_in[4];
    float* out = (float*)d_out;

    const int C = in_sizes[2] / NN;            // 512
    const size_t smem = (size_t)PLANES * NN * sizeof(float);   // 73728 B

    cudaFuncSetAttribute(gcn_bn_lrelu_kernel,
                         cudaFuncAttributeMaxDynamicSharedMemorySize, (int)smem);
    gcn_bn_lrelu_kernel<<<C * CSPLIT, NTHR, smem>>>(x, weight, gamma, beta, out, C);
}